// round 12
// baseline (speedup 1.0000x reference)
#include <cuda_runtime.h>
#include <cuda_fp16.h>
#include <cstdint>

#define N0T 4096
#define N1T 8192
#define N2T 4096
#define NTOT 16384
#define CD 64
#define OUTD 32
#define BSEG 64
#define NCTA 296
#define NUNIT 12288
#define NTILE 128
#define LHTOT 100663296   // 4096^2 + 8192^2 + 4096^2 halfs
#define LB1 16777216
#define LB2 83886080

// ---------------- scratch (static device memory; no allocs) ----------------
__device__ float g_dinv[NTOT];
__device__ float g_xB[NTOT * CD];   // layer0 output
__device__ float g_xA[NTOT * CD];   // layer1 output (pool input)
__device__ __half g_yh[(size_t)CD * NTOT];
__device__ __half g_Lh[LHTOT];      // fp16 copy of L, written by rowsum_cvt
__device__ float g_part[64 * BSEG * CD];
__device__ float g_gpart[(size_t)NCTA * 3 * 128 * 64];

// ---------------- helpers ----------------
__device__ __forceinline__ uint32_t smem_u32(const void* p) {
    uint32_t a;
    asm("{ .reg .u64 t; cvta.to.shared.u64 t, %1; cvt.u32.u64 %0, t; }" : "=r"(a) : "l"(p));
    return a;
}
__device__ __forceinline__ void cp16(uint32_t dst, const void* src) {
    asm volatile("cp.async.cg.shared.global [%0], [%1], 16;" :: "r"(dst), "l"(src));
}
__device__ __forceinline__ void cp_commit() { asm volatile("cp.async.commit_group;" ::: "memory"); }
__device__ __forceinline__ void cp_wait2() { asm volatile("cp.async.wait_group 2;" ::: "memory"); }

__device__ __forceinline__ void mma16816f(float* c, const uint32_t* a, uint32_t b0, uint32_t b1) {
    asm volatile(
        "mma.sync.aligned.m16n8k16.row.col.f32.f16.f16.f32 "
        "{%0,%1,%2,%3}, {%4,%5,%6,%7}, {%8,%9}, {%0,%1,%2,%3};"
        : "+f"(c[0]), "+f"(c[1]), "+f"(c[2]), "+f"(c[3])
        : "r"(a[0]), "r"(a[1]), "r"(a[2]), "r"(a[3]), "r"(b0), "r"(b1));
}

// unit u -> (tile t, chunk c); tiles: [0,32) rank0 (64 chunks), [32,96) rank1 (128), [96,128) rank2 (64)
__device__ __forceinline__ void decode_unit(int u, int& t, int& c) {
    if (u < 2048) { t = u >> 6; c = u & 63; }
    else if (u < 10240) { int v = u - 2048; t = 32 + (v >> 7); c = v & 127; }
    else { int v = u - 10240; t = 96 + (v >> 6); c = v & 63; }
}
__device__ __forceinline__ void tile_info(int t, int& Nr, int& m0, int& gb, int& ls) {
    if (t < 32) { Nr = N0T; m0 = t << 7; gb = 0; ls = 0; }
    else if (t < 96) { Nr = N1T; m0 = (t - 32) << 7; gb = N0T; ls = 1; }
    else { Nr = N2T; m0 = (t - 96) << 7; gb = N0T + N1T; ls = 2; }
}
__device__ __forceinline__ size_t lh_base(int ls) {
    return ls == 0 ? 0 : (ls == 1 ? (size_t)LB1 : (size_t)LB2);
}
__device__ __forceinline__ int cta_of(int u) {
    int bb = (int)(((long long)u * NCTA) / NUNIT);
    while (((bb + 1) * NUNIT) / NCTA <= u) bb++;
    while ((bb * NUNIT) / NCTA > u) bb--;
    return bb;
}

// launch-slot alignment probe (no-op)
__global__ void probe_kernel() {}

// ==========================================================================
// Kernel 1: rowsums of |L| -> dinv, AND fp32->fp16 conversion of L -> g_Lh
// ==========================================================================
__global__ void __launch_bounds__(256) rowsum_cvt_kernel(const float* __restrict__ L0,
                                                         const float* __restrict__ L1,
                                                         const float* __restrict__ L2) {
    int row = blockIdx.x;
    const float* L;
    int N, lr;
    size_t ob;
    if (row < N0T) { L = L0; N = N0T; lr = row; ob = 0; }
    else if (row < N0T + N1T) { L = L1; N = N1T; lr = row - N0T; ob = LB1; }
    else { L = L2; N = N2T; lr = row - N0T - N1T; ob = LB2; }
    const float4* p = (const float4*)(L + (size_t)lr * N);
    uint2* o = (uint2*)(g_Lh + ob + (size_t)lr * N);
    int n4 = N >> 2;
    float s0 = 0.f, s1 = 0.f;
    for (int i = threadIdx.x; i < n4; i += 256) {
        float4 v = __ldcs(p + i);
        s0 += fabsf(v.x) + fabsf(v.y);
        s1 += fabsf(v.z) + fabsf(v.w);
        __half2 a = __floats2half2_rn(v.x, v.y);
        __half2 b = __floats2half2_rn(v.z, v.w);
        uint2 w = make_uint2(*reinterpret_cast<uint32_t*>(&a),
                             *reinterpret_cast<uint32_t*>(&b));
        __stcs(o + i, w);
    }
    float s = s0 + s1;
    __shared__ float red[8];
    for (int off = 16; off; off >>= 1) s += __shfl_xor_sync(0xFFFFFFFFu, s, off);
    if ((threadIdx.x & 31) == 0) red[threadIdx.x >> 5] = s;
    __syncthreads();
    if (threadIdx.x < 8) {
        float t = red[threadIdx.x];
        for (int off = 4; off; off >>= 1) t += __shfl_xor_sync(0xFFu, t, off);
        if (threadIdx.x == 0) g_dinv[row] = (t != 0.f) ? rsqrtf(t) : 0.f;
    }
}

// ==========================================================================
// Kernel 2: y = (x @ W[layer]) * dinv[row] -> fp16, transposed store yT[c][row]
// layer 0 reads raw inputs; layer 1 reads g_xB
// ==========================================================================
__global__ void __launch_bounds__(256) xw_kernel(const float* __restrict__ W0,
                                                 const float* __restrict__ W1,
                                                 const float* __restrict__ W2,
                                                 const float* __restrict__ x0,
                                                 const float* __restrict__ x1,
                                                 const float* __restrict__ x2, int layer) {
    int row0 = blockIdx.x * 64;
    const float* W;
    const float* xsrc;
    int lrow0;
    if (row0 < N0T) { W = W0; xsrc = x0; lrow0 = row0; }
    else if (row0 < N0T + N1T) { W = W1; xsrc = x1; lrow0 = row0 - N0T; }
    else { W = W2; xsrc = x2; lrow0 = row0 - N0T - N1T; }
    if (layer) { xsrc = g_xB; lrow0 = row0; }

    __shared__ float Ws[64 * 64];
    __shared__ uint32_t tp[64 * 69];
    int tid = threadIdx.x;
    for (int i = tid; i < 4096; i += 256) Ws[i] = W[i];
    __syncthreads();

    int rl = tid >> 2, c0 = (tid & 3) * 16;
    int grow = row0 + rl;
    float xr[64];
    const float4* xp = (const float4*)(xsrc + (size_t)(lrow0 + rl) * CD);
#pragma unroll
    for (int i = 0; i < 16; i++) {
        float4 v = __ldg(xp + i);
        xr[4 * i + 0] = v.x; xr[4 * i + 1] = v.y; xr[4 * i + 2] = v.z; xr[4 * i + 3] = v.w;
    }
    float acc[16];
#pragma unroll
    for (int j = 0; j < 16; j++) acc[j] = 0.f;
#pragma unroll
    for (int k = 0; k < 64; k++) {
        float xv = xr[k];
#pragma unroll
        for (int j = 0; j < 16; j++) acc[j] += xv * Ws[k * 64 + c0 + j];
    }
    float dv = g_dinv[grow];
#pragma unroll
    for (int j = 0; j < 16; j++) {
        float v = acc[j] * dv;
        tp[(c0 + j) * 69 + rl] = (uint32_t)__half_as_ushort(__float2half_rn(v));
    }
    __syncthreads();

    int ch = tid >> 2, seg = tid & 3;  // 16 rows per thread
    uint32_t hh[8];
#pragma unroll
    for (int i = 0; i < 8; i++) {
        uint32_t p0 = tp[ch * 69 + seg * 16 + 2 * i];
        uint32_t p1 = tp[ch * 69 + seg * 16 + 2 * i + 1];
        hh[i] = (p0 & 0xFFFFu) | (p1 << 16);
    }
    size_t ob = (size_t)ch * NTOT + row0 + seg * 16;
    *(uint4*)(&g_yh[ob]) = make_uint4(hh[0], hh[1], hh[2], hh[3]);
    *(uint4*)(&g_yh[ob + 8]) = make_uint4(hh[4], hh[5], hh[6], hh[7]);
}

// ==========================================================================
// Kernel 3: balanced big GEMM via mma.sync fp16 (1 MMA / k16-tile)
// A now read as fp16 from g_Lh directly into fragment regs (no convert).
// 296 CTAs x 256 thr (2 CTAs/SM), equal (tile,chunk)-unit split, partials out.
// B: cp.async 4-stage smem pipeline.
// ==========================================================================
#define STG_BYTES 9216
#define SMEMSZ (4 * STG_BYTES)

__global__ void __launch_bounds__(256, 2) spmm_kernel() {
    extern __shared__ char smem[];
    const uint32_t sbase = smem_u32(smem);
    const int tid = threadIdx.x;
    const int lane = tid & 31, w = tid >> 5;
    const int b = blockIdx.x;
    const int u0 = (b * NUNIT) / NCTA;
    const int u1 = ((b + 1) * NUNIT) / NCTA;
    const int nun = u1 - u0;

    // issue one 64-k B chunk (8 KB fp16) into stage s
    auto issueB = [&](int u, int s) {
        int t, c; decode_unit(u, t, c);
        int Nr, m0, gb, ls; tile_info(t, Nr, m0, gb, ls);
        int n = tid >> 2, seg = tid & 3;
        size_t src = (size_t)n * NTOT + gb + c * 64 + seg * 16;
        uint32_t dst = sbase + s * STG_BYTES + n * 144 + seg * 32;
        cp16(dst, g_yh + src);
        cp16(dst + 16, g_yh + src + 8);
    };

    // load A fp16 fragments for one chunk straight into regs
    auto loadA = [&](int u, uint32_t* dst) {
        int t, c; decode_unit(u, t, c);
        int Nr, m0, gb, ls; tile_info(t, Nr, m0, gb, ls);
        const __half* Lh = g_Lh + lh_base(ls);
        int r0 = m0 + 16 * w + (lane >> 2);
        const __half* p0 = Lh + (size_t)r0 * Nr + c * 64 + (lane & 3) * 2;
        const __half* p1 = p0 + (size_t)8 * Nr;
#pragma unroll
        for (int kt = 0; kt < 4; kt++) {
            dst[kt * 4 + 0] = __ldcs((const uint32_t*)(p0 + kt * 16));
            dst[kt * 4 + 1] = __ldcs((const uint32_t*)(p1 + kt * 16));
            dst[kt * 4 + 2] = __ldcs((const uint32_t*)(p0 + kt * 16 + 8));
            dst[kt * 4 + 3] = __ldcs((const uint32_t*)(p1 + kt * 16 + 8));
        }
    };

    // prologue: 3 stages in flight
    for (int p = 0; p < 3; p++) {
        if (p < nun) issueB(u0 + p, p);
        cp_commit();
    }

    uint32_t cur[16], nxt[16];
    loadA(u0, cur);

    float acc[8][4];
#pragma unroll
    for (int nt = 0; nt < 8; nt++)
#pragma unroll
        for (int q = 0; q < 4; q++) acc[nt][q] = 0.f;

    int curtile, cc0;
    decode_unit(u0, curtile, cc0);
    int j = 0;

    const int fragoff = (lane >> 2) * 144 + (lane & 3) * 4;

    for (int i = 0; i < nun; i++) {
        cp_wait2();
        __syncthreads();
        if (i + 3 < nun) issueB(u0 + i + 3, (i + 3) & 3);
        cp_commit();
        if (i + 1 < nun) loadA(u0 + i + 1, nxt);

        const char* stg = smem + (i & 3) * STG_BYTES;
#pragma unroll
        for (int kt = 0; kt < 4; kt++) {
            const uint32_t* a = &cur[kt * 4];
#pragma unroll
            for (int nt = 0; nt < 8; nt++) {
                const char* p = stg + nt * 8 * 144 + kt * 32 + fragoff;
                uint32_t b0 = *(const uint32_t*)(p);
                uint32_t b1 = *(const uint32_t*)(p + 16);
                mma16816f(acc[nt], a, b0, b1);
            }
        }

        int ntile = -1;
        if (i + 1 < nun) { int cc; decode_unit(u0 + i + 1, ntile, cc); }
        if (ntile != curtile) {
            float* pp = g_gpart + ((size_t)(b * 3 + j) << 13);
            int r0 = 16 * w + (lane >> 2);
            int cb = (lane & 3) * 2;
#pragma unroll
            for (int nt = 0; nt < 8; nt++) {
                int col = nt * 8 + cb;
                *(float2*)(pp + r0 * 64 + col) = make_float2(acc[nt][0], acc[nt][1]);
                *(float2*)(pp + (r0 + 8) * 64 + col) = make_float2(acc[nt][2], acc[nt][3]);
#pragma unroll
                for (int q = 0; q < 4; q++) acc[nt][q] = 0.f;
            }
            j++;
            curtile = ntile;
        }
#pragma unroll
        for (int q = 0; q < 16; q++) cur[q] = nxt[q];
    }
}

// ==========================================================================
// Kernel 3b: combine partials per tile, apply dinv_i + relu
// ==========================================================================
__global__ void __launch_bounds__(256) combine_kernel(int dir) {
    float* __restrict__ xout = dir ? g_xA : g_xB;
    int t = blockIdx.x;
    int Nr, m0, gb, ls;
    tile_info(t, Nr, m0, gb, ls);
    int tu0, tlen;
    if (t < 32) { tu0 = t * 64; tlen = 64; }
    else if (t < 96) { tu0 = 2048 + (t - 32) * 128; tlen = 128; }
    else { tu0 = 10240 + (t - 96) * 64; tlen = 64; }
    int blo = cta_of(tu0), bhi = cta_of(tu0 + tlen - 1);

    int row = threadIdx.x >> 1, cb = (threadIdx.x & 1) * 32;
    float4 a[8];
#pragma unroll
    for (int q = 0; q < 8; q++) a[q] = make_float4(0.f, 0.f, 0.f, 0.f);
    for (int bb = blo; bb <= bhi; bb++) {
        int us = (bb * NUNIT) / NCTA;
        int ft, fc;
        decode_unit(us, ft, fc);
        const float4* p = (const float4*)(g_gpart + ((size_t)(bb * 3 + (t - ft)) << 13) +
                                          row * 64 + cb);
#pragma unroll
        for (int q = 0; q < 8; q++) {
            float4 v = p[q];
            a[q].x += v.x; a[q].y += v.y; a[q].z += v.z; a[q].w += v.w;
        }
    }
    float dv = g_dinv[gb + m0 + row];
    float4* o = (float4*)(xout + (size_t)(gb + m0 + row) * CD + cb);
#pragma unroll
    for (int q = 0; q < 8; q++)
        o[q] = make_float4(fmaxf(dv * a[q].x, 0.f), fmaxf(dv * a[q].y, 0.f),
                           fmaxf(dv * a[q].z, 0.f), fmaxf(dv * a[q].w, 0.f));
}

// ==========================================================================
// Kernel 4: deterministic segment pooling — reads x exactly once.
// 64 blocks (16 rank0, 32 rank1, 16 rank2) x 64 threads; smem bins, no atomics.
// ==========================================================================
__global__ void __launch_bounds__(64) pool_kernel(const int* __restrict__ bel0,
                                                  const int* __restrict__ bel1,
                                                  const int* __restrict__ bel2) {
    int blk = blockIdx.x;
    const int* bel;
    int gb, lrow0;
    if (blk < 16) { bel = bel0; gb = 0; lrow0 = blk * 256; }
    else if (blk < 48) { bel = bel1; gb = N0T; lrow0 = (blk - 16) * 256; }
    else { bel = bel2; gb = N0T + N1T; lrow0 = (blk - 48) * 256; }
    int t = threadIdx.x;

    __shared__ float bins[BSEG * CD];
    for (int i = t; i < BSEG * CD; i += 64) bins[i] = 0.f;
    __syncthreads();

    const float* xp = g_xA + (size_t)(gb + lrow0) * CD + t;
    const int* bp = bel + lrow0;
#pragma unroll 4
    for (int i = 0; i < 256; i++) {
        int bseg = __ldg(bp + i);
        float v = __ldg(xp + (size_t)i * CD);
        bins[bseg * CD + t] += v;
    }
    __syncthreads();
    for (int i = t; i < BSEG * CD; i += 64) g_part[blk * (BSEG * CD) + i] = bins[i];
}

// ==========================================================================
// Kernel 5: readout  out[b][o] = sum_r pooled_r @ Wr_r + br_r
// ==========================================================================
__global__ void __launch_bounds__(256) readout_kernel(const float* __restrict__ Wr0,
                                                      const float* __restrict__ br0,
                                                      const float* __restrict__ Wr1,
                                                      const float* __restrict__ br1,
                                                      const float* __restrict__ Wr2,
                                                      const float* __restrict__ br2,
                                                      float* __restrict__ out) {
    __shared__ float ps[3 * 8 * 64];  // [r][b_local][c]
    int tid = threadIdx.x;
    int b0 = blockIdx.x * 8;
    for (int i = tid; i < 1536; i += 256) {
        int r = i / 512;
        int rem = i % 512;
        int bl = rem / 64;
        int c = rem % 64;
        int kb = (r == 0) ? 0 : (r == 1 ? 16 : 48);
        int kn = (r == 1) ? 32 : 16;
        float s = 0.f;
        for (int k = 0; k < kn; k++)
            s += g_part[(kb + k) * (BSEG * CD) + (b0 + bl) * 64 + c];
        ps[i] = s;
    }
    __syncthreads();
    int bl = tid >> 5, o = tid & 31;
    float acc = __ldg(br0 + o) + __ldg(br1 + o) + __ldg(br2 + o);
    const float* Wr[3] = {Wr0, Wr1, Wr2};
#pragma unroll
    for (int r = 0; r < 3; r++) {
        const float* w = Wr[r];
        const float* p = &ps[r * 512 + bl * 64];
#pragma unroll 8
        for (int c = 0; c < 64; c++) acc += p[c] * __ldg(w + c * OUTD + o);
    }
    out[(b0 + bl) * OUTD + o] = acc;
}

// ==========================================================================
// host
// ==========================================================================
extern "C" void kernel_launch(void* const* d_in, const int* in_sizes, int n_in,
                              void* d_out, int out_size) {
    const float* x0 = (const float*)d_in[0];
    const float* x1 = (const float*)d_in[1];
    const float* x2 = (const float*)d_in[2];
    const float* L0 = (const float*)d_in[3];
    const float* L1 = (const float*)d_in[4];
    const float* L2 = (const float*)d_in[5];
    const int* bel0 = (const int*)d_in[6];
    const int* bel1 = (const int*)d_in[7];
    const int* bel2 = (const int*)d_in[8];
    const float* W0 = (const float*)d_in[9];
    const float* W1 = (const float*)d_in[10];
    const float* W2 = (const float*)d_in[11];
    const float* Wr0 = (const float*)d_in[12];
    const float* br0 = (const float*)d_in[13];
    const float* Wr1 = (const float*)d_in[14];
    const float* br1 = (const float*)d_in[15];
    const float* Wr2 = (const float*)d_in[16];
    const float* br2 = (const float*)d_in[17];

    cudaFuncSetAttribute(spmm_kernel, cudaFuncAttributeMaxDynamicSharedMemorySize, SMEMSZ);

    probe_kernel<<<1, 32>>>();  // shifts launch indices so ncu -s5 lands on spmm (layer0)
    rowsum_cvt_kernel<<<NTOT, 256>>>(L0, L1, L2);

    for (int layer = 0; layer < 2; layer++) {
        xw_kernel<<<NTOT / 64, 256>>>(W0 + layer * CD * CD, W1 + layer * CD * CD,
                                      W2 + layer * CD * CD, x0, x1, x2, layer);
        spmm_kernel<<<NCTA, 256, SMEMSZ>>>();
        combine_kernel<<<NTILE, 256>>>(layer);
    }

    pool_kernel<<<64, 64>>>(bel0, bel1, bel2);
    readout_kernel<<<8, 256>>>(Wr0, br0, Wr1, br1, Wr2, br2, (float*)d_out);
}

// round 13
// speedup vs baseline: 1.0332x; 1.0332x over previous
#include <cuda_runtime.h>
#include <cuda_fp16.h>
#include <cstdint>

#define N0T 4096
#define N1T 8192
#define N2T 4096
#define NTOT 16384
#define CD 64
#define OUTD 32
#define BSEG 64
#define NCTA 148
#define NUNIT 6144
#define NTILE 64
#define LHTOT 100663296   // 4096^2 + 8192^2 + 4096^2 halfs
#define LB1 16777216
#define LB2 83886080

// ---------------- scratch (static device memory; no allocs) ----------------
__device__ float g_dinv[NTOT];
__device__ float g_xB[NTOT * CD];   // layer0 output
__device__ float g_xA[NTOT * CD];   // layer1 output (pool input)
__device__ __half g_yh[(size_t)CD * NTOT];
__device__ __half g_Lh[LHTOT];      // fp16 copy of L, written by rowsum_cvt
__device__ float g_part[64 * BSEG * CD];
__device__ float g_gpart[(size_t)NCTA * 3 * 256 * 64];

// ---------------- helpers ----------------
__device__ __forceinline__ uint32_t smem_u32(const void* p) {
    uint32_t a;
    asm("{ .reg .u64 t; cvta.to.shared.u64 t, %1; cvt.u32.u64 %0, t; }" : "=r"(a) : "l"(p));
    return a;
}
__device__ __forceinline__ void cp16(uint32_t dst, const void* src) {
    asm volatile("cp.async.cg.shared.global [%0], [%1], 16;" :: "r"(dst), "l"(src));
}
__device__ __forceinline__ void cp_commit() { asm volatile("cp.async.commit_group;" ::: "memory"); }

__device__ __forceinline__ void mma16816f(float* c, const uint32_t* a, uint32_t b0, uint32_t b1) {
    asm volatile(
        "mma.sync.aligned.m16n8k16.row.col.f32.f16.f16.f32 "
        "{%0,%1,%2,%3}, {%4,%5,%6,%7}, {%8,%9}, {%0,%1,%2,%3};"
        : "+f"(c[0]), "+f"(c[1]), "+f"(c[2]), "+f"(c[3])
        : "r"(a[0]), "r"(a[1]), "r"(a[2]), "r"(a[3]), "r"(b0), "r"(b1));
}
#define LDSM4(R0, R1, R2, R3, ADDR)                                              \
    asm volatile("ldmatrix.sync.aligned.m8n8.x4.shared.b16 {%0,%1,%2,%3}, [%4];" \
                 : "=r"(R0), "=r"(R1), "=r"(R2), "=r"(R3) : "r"(ADDR))

// unit u -> (tile t, chunk c); 256-row tiles:
// rank0: tiles [0,16) x 64 chunks; rank1: [16,48) x 128; rank2: [48,64) x 64
__device__ __forceinline__ void decode_unit(int u, int& t, int& c) {
    if (u < 1024) { t = u >> 6; c = u & 63; }
    else if (u < 5120) { int v = u - 1024; t = 16 + (v >> 7); c = v & 127; }
    else { int v = u - 5120; t = 48 + (v >> 6); c = v & 63; }
}
__device__ __forceinline__ void tile_info(int t, int& Nr, int& m0, int& gb, int& ls) {
    if (t < 16) { Nr = N0T; m0 = t << 8; gb = 0; ls = 0; }
    else if (t < 48) { Nr = N1T; m0 = (t - 16) << 8; gb = N0T; ls = 1; }
    else { Nr = N2T; m0 = (t - 48) << 8; gb = N0T + N1T; ls = 2; }
}
__device__ __forceinline__ size_t lh_base(int ls) {
    return ls == 0 ? 0 : (ls == 1 ? (size_t)LB1 : (size_t)LB2);
}
__device__ __forceinline__ int cta_of(int u) {
    int bb = (int)(((long long)u * NCTA) / NUNIT);
    while (((bb + 1) * NUNIT) / NCTA <= u) bb++;
    while ((bb * NUNIT) / NCTA > u) bb--;
    return bb;
}

// launch-slot alignment probe (no-op)
__global__ void probe_kernel() {}

// ==========================================================================
// Kernel 1: rowsums of |L| -> dinv, AND fp32->fp16 conversion of L -> g_Lh
// ==========================================================================
__global__ void __launch_bounds__(256) rowsum_cvt_kernel(const float* __restrict__ L0,
                                                         const float* __restrict__ L1,
                                                         const float* __restrict__ L2) {
    int row = blockIdx.x;
    const float* L;
    int N, lr;
    size_t ob;
    if (row < N0T) { L = L0; N = N0T; lr = row; ob = 0; }
    else if (row < N0T + N1T) { L = L1; N = N1T; lr = row - N0T; ob = LB1; }
    else { L = L2; N = N2T; lr = row - N0T - N1T; ob = LB2; }
    const float4* p = (const float4*)(L + (size_t)lr * N);
    uint2* o = (uint2*)(g_Lh + ob + (size_t)lr * N);
    int n4 = N >> 2;
    float s0 = 0.f, s1 = 0.f;
    for (int i = threadIdx.x; i < n4; i += 256) {
        float4 v = __ldcs(p + i);
        s0 += fabsf(v.x) + fabsf(v.y);
        s1 += fabsf(v.z) + fabsf(v.w);
        __half2 a = __floats2half2_rn(v.x, v.y);
        __half2 b = __floats2half2_rn(v.z, v.w);
        uint2 w = make_uint2(*reinterpret_cast<uint32_t*>(&a),
                             *reinterpret_cast<uint32_t*>(&b));
        __stcs(o + i, w);
    }
    float s = s0 + s1;
    __shared__ float red[8];
    for (int off = 16; off; off >>= 1) s += __shfl_xor_sync(0xFFFFFFFFu, s, off);
    if ((threadIdx.x & 31) == 0) red[threadIdx.x >> 5] = s;
    __syncthreads();
    if (threadIdx.x < 8) {
        float t = red[threadIdx.x];
        for (int off = 4; off; off >>= 1) t += __shfl_xor_sync(0xFFu, t, off);
        if (threadIdx.x == 0) g_dinv[row] = (t != 0.f) ? rsqrtf(t) : 0.f;
    }
}

// ==========================================================================
// Kernel 2: y = (x @ W[layer]) * dinv[row] -> fp16, transposed store yT[c][row]
// ==========================================================================
__global__ void __launch_bounds__(256) xw_kernel(const float* __restrict__ W0,
                                                 const float* __restrict__ W1,
                                                 const float* __restrict__ W2,
                                                 const float* __restrict__ x0,
                                                 const float* __restrict__ x1,
                                                 const float* __restrict__ x2, int layer) {
    int row0 = blockIdx.x * 64;
    const float* W;
    const float* xsrc;
    int lrow0;
    if (row0 < N0T) { W = W0; xsrc = x0; lrow0 = row0; }
    else if (row0 < N0T + N1T) { W = W1; xsrc = x1; lrow0 = row0 - N0T; }
    else { W = W2; xsrc = x2; lrow0 = row0 - N0T - N1T; }
    if (layer) { xsrc = g_xB; lrow0 = row0; }

    __shared__ float Ws[64 * 64];
    __shared__ uint32_t tp[64 * 69];
    int tid = threadIdx.x;
    for (int i = tid; i < 4096; i += 256) Ws[i] = W[i];
    __syncthreads();

    int rl = tid >> 2, c0 = (tid & 3) * 16;
    int grow = row0 + rl;
    float xr[64];
    const float4* xp = (const float4*)(xsrc + (size_t)(lrow0 + rl) * CD);
#pragma unroll
    for (int i = 0; i < 16; i++) {
        float4 v = __ldg(xp + i);
        xr[4 * i + 0] = v.x; xr[4 * i + 1] = v.y; xr[4 * i + 2] = v.z; xr[4 * i + 3] = v.w;
    }
    float acc[16];
#pragma unroll
    for (int j = 0; j < 16; j++) acc[j] = 0.f;
#pragma unroll
    for (int k = 0; k < 64; k++) {
        float xv = xr[k];
#pragma unroll
        for (int j = 0; j < 16; j++) acc[j] += xv * Ws[k * 64 + c0 + j];
    }
    float dv = g_dinv[grow];
#pragma unroll
    for (int j = 0; j < 16; j++) {
        float v = acc[j] * dv;
        tp[(c0 + j) * 69 + rl] = (uint32_t)__half_as_ushort(__float2half_rn(v));
    }
    __syncthreads();

    int ch = tid >> 2, seg = tid & 3;  // 16 rows per thread
    uint32_t hh[8];
#pragma unroll
    for (int i = 0; i < 8; i++) {
        uint32_t p0 = tp[ch * 69 + seg * 16 + 2 * i];
        uint32_t p1 = tp[ch * 69 + seg * 16 + 2 * i + 1];
        hh[i] = (p0 & 0xFFFFu) | (p1 << 16);
    }
    size_t ob = (size_t)ch * NTOT + row0 + seg * 16;
    *(uint4*)(&g_yh[ob]) = make_uint4(hh[0], hh[1], hh[2], hh[3]);
    *(uint4*)(&g_yh[ob + 8]) = make_uint4(hh[4], hh[5], hh[6], hh[7]);
}

// ==========================================================================
// Kernel 3: balanced big GEMM, fp16 mma.sync + ldmatrix + cp.async staging.
// 148 CTAs x 256 thr (8 warps), CTA tile = 256 rows x 64 N, M_per_warp = 32.
// A (32KB) and B (8KB) per 64-K chunk staged via cp.async, xor-swizzled,
// fragments via ldmatrix.x4. 5-stage pipeline. Partials to g_gpart.
// ==========================================================================
#define STG_BYTES 40960
#define NSTG 5
#define SMEMSZ (NSTG * STG_BYTES)

__global__ void __launch_bounds__(256, 1) spmm_kernel() {
    extern __shared__ char smem[];
    const uint32_t sbase = smem_u32(smem);
    const int tid = threadIdx.x;
    const int lane = tid & 31, w = tid >> 5;
    const int b = blockIdx.x;
    const int u0 = (b * NUNIT) / NCTA;
    const int u1 = ((b + 1) * NUNIT) / NCTA;
    const int nun = u1 - u0;

    // stage one chunk: A 256x64k halfs (32KB) + B 64x64k halfs (8KB)
    auto issue = [&](int u, int s) {
        int t, c;
        decode_unit(u, t, c);
        int Nr, m0, gb, ls;
        tile_info(t, Nr, m0, gb, ls);
        uint32_t stg = sbase + s * STG_BYTES;
        {   // A: one 128B row per thread, 8 swizzled 16B segs
            const __half* src = g_Lh + lh_base(ls) + (size_t)(m0 + tid) * Nr + c * 64;
            uint32_t dst = stg + tid * 128;
            int sw = tid & 7;
#pragma unroll
            for (int sg = 0; sg < 8; sg++)
                cp16(dst + (((sg ^ sw)) << 4), src + sg * 8);
        }
        {   // B: 64 rows x 128B; thread -> row tid>>2, segs (tid&3)*2, +1
            int n = tid >> 2, s0 = (tid & 3) * 2;
            const __half* src = g_yh + (size_t)n * NTOT + gb + c * 64;
            uint32_t dst = stg + 32768 + n * 128;
            int sw = n & 7;
            cp16(dst + ((s0 ^ sw) << 4), src + s0 * 8);
            cp16(dst + (((s0 + 1) ^ sw) << 4), src + (s0 + 1) * 8);
        }
    };

    // prologue: 4 chunks in flight
    for (int p = 0; p < 4; p++) {
        if (p < nun) issue(u0 + p, p);
        cp_commit();
    }

    float acc[16][4];
#pragma unroll
    for (int q = 0; q < 16; q++)
#pragma unroll
        for (int r = 0; r < 4; r++) acc[q][r] = 0.f;

    int curtile, cc0;
    decode_unit(u0, curtile, cc0);
    int j = 0;

    // ldmatrix per-thread geometry
    const int ar = lane & 15;                       // A row-in-16
    const int ahi = lane >> 4;                      // A k-half selector
    const uint32_t arow0 = (uint32_t)(w * 32 + ar) * 128;
    const uint32_t arow1 = arow0 + 16 * 128;
    const int asw = ar & 7;
    const int bro = ((lane >> 4) << 3) + (lane & 7);  // B row-in-16
    const int bhi = (lane >> 3) & 1;                  // B k-half selector
    const int bsw = lane & 7;

    for (int i = 0; i < nun; i++) {
        asm volatile("cp.async.wait_group 3;" ::: "memory");
        __syncthreads();
        if (i + 4 < nun) issue(u0 + i + 4, (i + 4) % NSTG);
        cp_commit();

        uint32_t Ab = sbase + (i % NSTG) * STG_BYTES;
        uint32_t Bb = Ab + 32768;
#pragma unroll
        for (int kt = 0; kt < 4; kt++) {
            uint32_t a0[4], a1[4];
            uint32_t ka = (uint32_t)(((2 * kt + ahi) ^ asw) << 4);
            LDSM4(a0[0], a0[1], a0[2], a0[3], Ab + arow0 + ka);
            LDSM4(a1[0], a1[1], a1[2], a1[3], Ab + arow1 + ka);
            uint32_t kb = (uint32_t)(((2 * kt + bhi) ^ bsw) << 4);
#pragma unroll
            for (int np = 0; np < 4; np++) {
                uint32_t b0, b1, b2, b3;
                LDSM4(b0, b1, b2, b3, Bb + (uint32_t)(np * 16 + bro) * 128 + kb);
                mma16816f(acc[2 * np + 0], a0, b0, b1);
                mma16816f(acc[2 * np + 1], a0, b2, b3);
                mma16816f(acc[8 + 2 * np + 0], a1, b0, b1);
                mma16816f(acc[8 + 2 * np + 1], a1, b2, b3);
            }
        }

        int ntile = -1;
        if (i + 1 < nun) { int cc; decode_unit(u0 + i + 1, ntile, cc); }
        if (ntile != curtile) {
            float* pp = g_gpart + ((size_t)(b * 3 + j) << 14);
            int r = lane >> 2, c0 = (lane & 3) * 2;
#pragma unroll
            for (int mt = 0; mt < 2; mt++)
#pragma unroll
                for (int nt = 0; nt < 8; nt++) {
                    int row = w * 32 + mt * 16 + r;
                    int col = nt * 8 + c0;
                    *(float2*)(pp + row * 64 + col) =
                        make_float2(acc[mt * 8 + nt][0], acc[mt * 8 + nt][1]);
                    *(float2*)(pp + (row + 8) * 64 + col) =
                        make_float2(acc[mt * 8 + nt][2], acc[mt * 8 + nt][3]);
#pragma unroll
                    for (int q = 0; q < 4; q++) acc[mt * 8 + nt][q] = 0.f;
                }
            j++;
            curtile = ntile;
        }
    }
}

// ==========================================================================
// Kernel 3b: combine partials per 256-row tile, apply dinv_i + relu
// ==========================================================================
__global__ void __launch_bounds__(256) combine_kernel(int dir) {
    float* __restrict__ xout = dir ? g_xA : g_xB;
    int t = blockIdx.x;
    int Nr, m0, gb, ls;
    tile_info(t, Nr, m0, gb, ls);
    int tu0;
    if (t < 16) tu0 = t * 64;
    else if (t < 48) tu0 = 1024 + (t - 16) * 128;
    else tu0 = 5120 + (t - 48) * 64;
    int tlen = (t >= 16 && t < 48) ? 128 : 64;
    int blo = cta_of(tu0), bhi = cta_of(tu0 + tlen - 1);

    int row = threadIdx.x;
    float4 a[16];
#pragma unroll
    for (int q = 0; q < 16; q++) a[q] = make_float4(0.f, 0.f, 0.f, 0.f);
    for (int bb = blo; bb <= bhi; bb++) {
        int us = (bb * NUNIT) / NCTA;
        int ft, fc;
        decode_unit(us, ft, fc);
        const float4* p = (const float4*)(g_gpart + ((size_t)(bb * 3 + (t - ft)) << 14) +
                                          row * 64);
#pragma unroll
        for (int q = 0; q < 16; q++) {
            float4 v = p[q];
            a[q].x += v.x; a[q].y += v.y; a[q].z += v.z; a[q].w += v.w;
        }
    }
    float dv = g_dinv[gb + m0 + row];
    float4* o = (float4*)(xout + (size_t)(gb + m0 + row) * CD);
#pragma unroll
    for (int q = 0; q < 16; q++)
        o[q] = make_float4(fmaxf(dv * a[q].x, 0.f), fmaxf(dv * a[q].y, 0.f),
                           fmaxf(dv * a[q].z, 0.f), fmaxf(dv * a[q].w, 0.f));
}

// ==========================================================================
// Kernel 4: deterministic segment pooling — reads x exactly once.
// ==========================================================================
__global__ void __launch_bounds__(64) pool_kernel(const int* __restrict__ bel0,
                                                  const int* __restrict__ bel1,
                                                  const int* __restrict__ bel2) {
    int blk = blockIdx.x;
    const int* bel;
    int gb, lrow0;
    if (blk < 16) { bel = bel0; gb = 0; lrow0 = blk * 256; }
    else if (blk < 48) { bel = bel1; gb = N0T; lrow0 = (blk - 16) * 256; }
    else { bel = bel2; gb = N0T + N1T; lrow0 = (blk - 48) * 256; }
    int t = threadIdx.x;

    __shared__ float bins[BSEG * CD];
    for (int i = t; i < BSEG * CD; i += 64) bins[i] = 0.f;
    __syncthreads();

    const float* xp = g_xA + (size_t)(gb + lrow0) * CD + t;
    const int* bp = bel + lrow0;
#pragma unroll 4
    for (int i = 0; i < 256; i++) {
        int bseg = __ldg(bp + i);
        float v = __ldg(xp + (size_t)i * CD);
        bins[bseg * CD + t] += v;
    }
    __syncthreads();
    for (int i = t; i < BSEG * CD; i += 64) g_part[blk * (BSEG * CD) + i] = bins[i];
}

// ==========================================================================
// Kernel 5: readout  out[b][o] = sum_r pooled_r @ Wr_r + br_r
// ==========================================================================
__global__ void __launch_bounds__(256) readout_kernel(const float* __restrict__ Wr0,
                                                      const float* __restrict__ br0,
                                                      const float* __restrict__ Wr1,
                                                      const float* __restrict__ br1,
                                                      const float* __restrict__ Wr2,
                                                      const float* __restrict__ br2,
                                                      float* __restrict__ out) {
    __shared__ float ps[3 * 8 * 64];  // [r][b_local][c]
    int tid = threadIdx.x;
    int b0 = blockIdx.x * 8;
    for (int i = tid; i < 1536; i += 256) {
        int r = i / 512;
        int rem = i % 512;
        int bl = rem / 64;
        int c = rem % 64;
        int kb = (r == 0) ? 0 : (r == 1 ? 16 : 48);
        int kn = (r == 1) ? 32 : 16;
        float s = 0.f;
        for (int k = 0; k < kn; k++)
            s += g_part[(kb + k) * (BSEG * CD) + (b0 + bl) * 64 + c];
        ps[i] = s;
    }
    __syncthreads();
    int bl = tid >> 5, o = tid & 31;
    float acc = __ldg(br0 + o) + __ldg(br1 + o) + __ldg(br2 + o);
    const float* Wr[3] = {Wr0, Wr1, Wr2};
#pragma unroll
    for (int r = 0; r < 3; r++) {
        const float* w = Wr[r];
        const float* p = &ps[r * 512 + bl * 64];
#pragma unroll 8
        for (int c = 0; c < 64; c++) acc += p[c] * __ldg(w + c * OUTD + o);
    }
    out[(b0 + bl) * OUTD + o] = acc;
}

// ==========================================================================
// host
// ==========================================================================
extern "C" void kernel_launch(void* const* d_in, const int* in_sizes, int n_in,
                              void* d_out, int out_size) {
    const float* x0 = (const float*)d_in[0];
    const float* x1 = (const float*)d_in[1];
    const float* x2 = (const float*)d_in[2];
    const float* L0 = (const float*)d_in[3];
    const float* L1 = (const float*)d_in[4];
    const float* L2 = (const float*)d_in[5];
    const int* bel0 = (const int*)d_in[6];
    const int* bel1 = (const int*)d_in[7];
    const int* bel2 = (const int*)d_in[8];
    const float* W0 = (const float*)d_in[9];
    const float* W1 = (const float*)d_in[10];
    const float* W2 = (const float*)d_in[11];
    const float* Wr0 = (const float*)d_in[12];
    const float* br0 = (const float*)d_in[13];
    const float* Wr1 = (const float*)d_in[14];
    const float* br1 = (const float*)d_in[15];
    const float* Wr2 = (const float*)d_in[16];
    const float* br2 = (const float*)d_in[17];

    cudaFuncSetAttribute(spmm_kernel, cudaFuncAttributeMaxDynamicSharedMemorySize, SMEMSZ);

    probe_kernel<<<1, 32>>>();  // keeps ncu capture slot on spmm (layer0)
    rowsum_cvt_kernel<<<NTOT, 256>>>(L0, L1, L2);

    for (int layer = 0; layer < 2; layer++) {
        xw_kernel<<<NTOT / 64, 256>>>(W0 + layer * CD * CD, W1 + layer * CD * CD,
                                      W2 + layer * CD * CD, x0, x1, x2, layer);
        spmm_kernel<<<NCTA, 256, SMEMSZ>>>();
        combine_kernel<<<NTILE, 256>>>(layer);
    }

    pool_kernel<<<64, 64>>>(bel0, bel1, bel2);
    readout_kernel<<<8, 256>>>(Wr0, br0, Wr1, br1, Wr2, br2, (float*)d_out);
}

// round 14
// speedup vs baseline: 1.1969x; 1.1584x over previous
#include <cuda_runtime.h>
#include <cuda_fp16.h>
#include <cstdint>

#define N0T 4096
#define N1T 8192
#define N2T 4096
#define NTOT 16384
#define CD 64
#define OUTD 32
#define BSEG 64
#define NCTA 296
#define NUNIT 12288
#define NTILE 128
#define LHTOT 100663296   // 4096^2 + 8192^2 + 4096^2 halfs
#define LB1 16777216
#define LB2 83886080

// ---------------- scratch (static device memory; no allocs) ----------------
__device__ float g_dinv[NTOT];
__device__ float g_xB[NTOT * CD];   // layer0 output
__device__ float g_xA[NTOT * CD];   // layer1 output (pool input)
__device__ __half g_yh[(size_t)CD * NTOT];
__device__ __half g_Lh[LHTOT];      // fp16 copy of L, written by rowsum_cvt
__device__ float g_part[64 * BSEG * CD];
__device__ float g_gpart[(size_t)NCTA * 3 * 128 * 64];

// ---------------- helpers ----------------
__device__ __forceinline__ uint32_t smem_u32(const void* p) {
    uint32_t a;
    asm("{ .reg .u64 t; cvta.to.shared.u64 t, %1; cvt.u32.u64 %0, t; }" : "=r"(a) : "l"(p));
    return a;
}
__device__ __forceinline__ void cp16(uint32_t dst, const void* src) {
    asm volatile("cp.async.cg.shared.global [%0], [%1], 16;" :: "r"(dst), "l"(src));
}
__device__ __forceinline__ void cp_commit() { asm volatile("cp.async.commit_group;" ::: "memory"); }

__device__ __forceinline__ void mma16816f(float* c, const uint32_t* a, uint32_t b0, uint32_t b1) {
    asm volatile(
        "mma.sync.aligned.m16n8k16.row.col.f32.f16.f16.f32 "
        "{%0,%1,%2,%3}, {%4,%5,%6,%7}, {%8,%9}, {%0,%1,%2,%3};"
        : "+f"(c[0]), "+f"(c[1]), "+f"(c[2]), "+f"(c[3])
        : "r"(a[0]), "r"(a[1]), "r"(a[2]), "r"(a[3]), "r"(b0), "r"(b1));
}
#define LDSM4(R0, R1, R2, R3, ADDR)                                              \
    asm volatile("ldmatrix.sync.aligned.m8n8.x4.shared.b16 {%0,%1,%2,%3}, [%4];" \
                 : "=r"(R0), "=r"(R1), "=r"(R2), "=r"(R3) : "r"(ADDR))

// unit u -> (tile t, chunk c); 128-row tiles:
// rank0: tiles [0,32) x 64 chunks; rank1: [32,96) x 128; rank2: [96,128) x 64
__device__ __forceinline__ void decode_unit(int u, int& t, int& c) {
    if (u < 2048) { t = u >> 6; c = u & 63; }
    else if (u < 10240) { int v = u - 2048; t = 32 + (v >> 7); c = v & 127; }
    else { int v = u - 10240; t = 96 + (v >> 6); c = v & 63; }
}
__device__ __forceinline__ void tile_info(int t, int& Nr, int& m0, int& gb, int& ls) {
    if (t < 32) { Nr = N0T; m0 = t << 7; gb = 0; ls = 0; }
    else if (t < 96) { Nr = N1T; m0 = (t - 32) << 7; gb = N0T; ls = 1; }
    else { Nr = N2T; m0 = (t - 96) << 7; gb = N0T + N1T; ls = 2; }
}
__device__ __forceinline__ size_t lh_base(int ls) {
    return ls == 0 ? 0 : (ls == 1 ? (size_t)LB1 : (size_t)LB2);
}
__device__ __forceinline__ int cta_of(int u) {
    int bb = (int)(((long long)u * NCTA) / NUNIT);
    while (((bb + 1) * NUNIT) / NCTA <= u) bb++;
    while ((bb * NUNIT) / NCTA > u) bb--;
    return bb;
}

// launch-slot alignment probe (no-op)
__global__ void probe_kernel() {}

// ==========================================================================
// Kernel 1: rowsums of |L| -> dinv, AND fp32->fp16 conversion of L -> g_Lh
// ==========================================================================
__global__ void __launch_bounds__(256) rowsum_cvt_kernel(const float* __restrict__ L0,
                                                         const float* __restrict__ L1,
                                                         const float* __restrict__ L2) {
    int row = blockIdx.x;
    const float* L;
    int N, lr;
    size_t ob;
    if (row < N0T) { L = L0; N = N0T; lr = row; ob = 0; }
    else if (row < N0T + N1T) { L = L1; N = N1T; lr = row - N0T; ob = LB1; }
    else { L = L2; N = N2T; lr = row - N0T - N1T; ob = LB2; }
    const float4* p = (const float4*)(L + (size_t)lr * N);
    uint2* o = (uint2*)(g_Lh + ob + (size_t)lr * N);
    int n4 = N >> 2;
    float s0 = 0.f, s1 = 0.f;
    for (int i = threadIdx.x; i < n4; i += 256) {
        float4 v = __ldcs(p + i);
        s0 += fabsf(v.x) + fabsf(v.y);
        s1 += fabsf(v.z) + fabsf(v.w);
        __half2 a = __floats2half2_rn(v.x, v.y);
        __half2 b = __floats2half2_rn(v.z, v.w);
        uint2 w = make_uint2(*reinterpret_cast<uint32_t*>(&a),
                             *reinterpret_cast<uint32_t*>(&b));
        __stcs(o + i, w);
    }
    float s = s0 + s1;
    __shared__ float red[8];
    for (int off = 16; off; off >>= 1) s += __shfl_xor_sync(0xFFFFFFFFu, s, off);
    if ((threadIdx.x & 31) == 0) red[threadIdx.x >> 5] = s;
    __syncthreads();
    if (threadIdx.x < 8) {
        float t = red[threadIdx.x];
        for (int off = 4; off; off >>= 1) t += __shfl_xor_sync(0xFFu, t, off);
        if (threadIdx.x == 0) g_dinv[row] = (t != 0.f) ? rsqrtf(t) : 0.f;
    }
}

// ==========================================================================
// Kernel 2: y = (x @ W[layer]) * dinv[row] -> fp16, transposed store yT[c][row]
// ==========================================================================
__global__ void __launch_bounds__(256) xw_kernel(const float* __restrict__ W0,
                                                 const float* __restrict__ W1,
                                                 const float* __restrict__ W2,
                                                 const float* __restrict__ x0,
                                                 const float* __restrict__ x1,
                                                 const float* __restrict__ x2, int layer) {
    int row0 = blockIdx.x * 64;
    const float* W;
    const float* xsrc;
    int lrow0;
    if (row0 < N0T) { W = W0; xsrc = x0; lrow0 = row0; }
    else if (row0 < N0T + N1T) { W = W1; xsrc = x1; lrow0 = row0 - N0T; }
    else { W = W2; xsrc = x2; lrow0 = row0 - N0T - N1T; }
    if (layer) { xsrc = g_xB; lrow0 = row0; }

    __shared__ float Ws[64 * 64];
    __shared__ uint32_t tp[64 * 69];
    int tid = threadIdx.x;
    for (int i = tid; i < 4096; i += 256) Ws[i] = W[i];
    __syncthreads();

    int rl = tid >> 2, c0 = (tid & 3) * 16;
    int grow = row0 + rl;
    float xr[64];
    const float4* xp = (const float4*)(xsrc + (size_t)(lrow0 + rl) * CD);
#pragma unroll
    for (int i = 0; i < 16; i++) {
        float4 v = __ldg(xp + i);
        xr[4 * i + 0] = v.x; xr[4 * i + 1] = v.y; xr[4 * i + 2] = v.z; xr[4 * i + 3] = v.w;
    }
    float acc[16];
#pragma unroll
    for (int j = 0; j < 16; j++) acc[j] = 0.f;
#pragma unroll
    for (int k = 0; k < 64; k++) {
        float xv = xr[k];
#pragma unroll
        for (int j = 0; j < 16; j++) acc[j] += xv * Ws[k * 64 + c0 + j];
    }
    float dv = g_dinv[grow];
#pragma unroll
    for (int j = 0; j < 16; j++) {
        float v = acc[j] * dv;
        tp[(c0 + j) * 69 + rl] = (uint32_t)__half_as_ushort(__float2half_rn(v));
    }
    __syncthreads();

    int ch = tid >> 2, seg = tid & 3;  // 16 rows per thread
    uint32_t hh[8];
#pragma unroll
    for (int i = 0; i < 8; i++) {
        uint32_t p0 = tp[ch * 69 + seg * 16 + 2 * i];
        uint32_t p1 = tp[ch * 69 + seg * 16 + 2 * i + 1];
        hh[i] = (p0 & 0xFFFFu) | (p1 << 16);
    }
    size_t ob = (size_t)ch * NTOT + row0 + seg * 16;
    *(uint4*)(&g_yh[ob]) = make_uint4(hh[0], hh[1], hh[2], hh[3]);
    *(uint4*)(&g_yh[ob + 8]) = make_uint4(hh[4], hh[5], hh[6], hh[7]);
}

// ==========================================================================
// Kernel 3: balanced big GEMM, fp16 mma.sync + ldmatrix + cp.async staging.
// 296 CTAs x 256 thr (8 warps), 2 CTAs/SM, CTA tile = 128 rows, M_per_warp=16.
// A (16KB) + B (8KB) per 64-K chunk, 4-stage pipeline, xor-swizzled smem,
// fragments via ldmatrix.x4. Partials to g_gpart.
// ==========================================================================
#define STG_BYTES 24576
#define NSTG 4
#define SMEMSZ (NSTG * STG_BYTES)

__global__ void __launch_bounds__(256, 2) spmm_kernel() {
    extern __shared__ char smem[];
    const uint32_t sbase = smem_u32(smem);
    const int tid = threadIdx.x;
    const int lane = tid & 31, w = tid >> 5;
    const int b = blockIdx.x;
    const int u0 = (b * NUNIT) / NCTA;
    const int u1 = ((b + 1) * NUNIT) / NCTA;
    const int nun = u1 - u0;

    // stage one chunk: A 128rows x 64k halfs (16KB) + B 64rows x 64k (8KB)
    auto issue = [&](int u, int s) {
        int t, c;
        decode_unit(u, t, c);
        int Nr, m0, gb, ls;
        tile_info(t, Nr, m0, gb, ls);
        uint32_t stg = sbase + s * STG_BYTES;
        {   // A: thread -> row tid>>1, 4 swizzled 16B segs
            int row = tid >> 1, sg0 = (tid & 1) * 4;
            const __half* src = g_Lh + lh_base(ls) + (size_t)(m0 + row) * Nr + c * 64;
            uint32_t dst = stg + row * 128;
            int sw = row & 7;
#pragma unroll
            for (int q = 0; q < 4; q++)
                cp16(dst + (((sg0 + q) ^ sw) << 4), src + (sg0 + q) * 8);
        }
        {   // B: thread -> row tid>>2, segs (tid&3)*2, +1
            int n = tid >> 2, s0 = (tid & 3) * 2;
            const __half* src = g_yh + (size_t)n * NTOT + gb + c * 64;
            uint32_t dst = stg + 16384 + n * 128;
            int sw = n & 7;
            cp16(dst + ((s0 ^ sw) << 4), src + s0 * 8);
            cp16(dst + (((s0 + 1) ^ sw) << 4), src + (s0 + 1) * 8);
        }
    };

    // prologue: 3 chunks in flight
    for (int p = 0; p < 3; p++) {
        if (p < nun) issue(u0 + p, p);
        cp_commit();
    }

    float acc[8][4];
#pragma unroll
    for (int q = 0; q < 8; q++)
#pragma unroll
        for (int r = 0; r < 4; r++) acc[q][r] = 0.f;

    int curtile, cc0;
    decode_unit(u0, curtile, cc0);
    int j = 0;

    // ldmatrix per-thread geometry
    const int ar = lane & 15;                         // A row-in-16
    const int ahi = lane >> 4;                        // A k-half selector
    const uint32_t arow = (uint32_t)(w * 16 + ar) * 128;
    const int asw = ar & 7;
    const int bro = ((lane >> 4) << 3) + (lane & 7);  // B row-in-16
    const int bhi = (lane >> 3) & 1;                  // B k-half selector
    const int bsw = lane & 7;

    for (int i = 0; i < nun; i++) {
        asm volatile("cp.async.wait_group 2;" ::: "memory");
        __syncthreads();
        if (i + 3 < nun) issue(u0 + i + 3, (i + 3) % NSTG);
        cp_commit();

        uint32_t Ab = sbase + (i % NSTG) * STG_BYTES;
        uint32_t Bb = Ab + 16384;
#pragma unroll
        for (int kt = 0; kt < 4; kt++) {
            uint32_t a0[4];
            uint32_t ka = (uint32_t)(((2 * kt + ahi) ^ asw) << 4);
            LDSM4(a0[0], a0[1], a0[2], a0[3], Ab + arow + ka);
            uint32_t kb = (uint32_t)(((2 * kt + bhi) ^ bsw) << 4);
#pragma unroll
            for (int np = 0; np < 4; np++) {
                uint32_t b0, b1, b2, b3;
                LDSM4(b0, b1, b2, b3, Bb + (uint32_t)(np * 16 + bro) * 128 + kb);
                mma16816f(acc[2 * np + 0], a0, b0, b1);
                mma16816f(acc[2 * np + 1], a0, b2, b3);
            }
        }

        int ntile = -1;
        if (i + 1 < nun) { int cc; decode_unit(u0 + i + 1, ntile, cc); }
        if (ntile != curtile) {
            float* pp = g_gpart + ((size_t)(b * 3 + j) << 13);
            int r = lane >> 2, c0 = (lane & 3) * 2;
#pragma unroll
            for (int nt = 0; nt < 8; nt++) {
                int row = w * 16 + r;
                int col = nt * 8 + c0;
                *(float2*)(pp + row * 64 + col) = make_float2(acc[nt][0], acc[nt][1]);
                *(float2*)(pp + (row + 8) * 64 + col) = make_float2(acc[nt][2], acc[nt][3]);
#pragma unroll
                for (int q = 0; q < 4; q++) acc[nt][q] = 0.f;
            }
            j++;
            curtile = ntile;
        }
    }
}

// ==========================================================================
// Kernel 3b: combine partials per 128-row tile, apply dinv_i + relu
// ==========================================================================
__global__ void __launch_bounds__(256) combine_kernel(int dir) {
    float* __restrict__ xout = dir ? g_xA : g_xB;
    int t = blockIdx.x;
    int Nr, m0, gb, ls;
    tile_info(t, Nr, m0, gb, ls);
    int tu0, tlen;
    if (t < 32) { tu0 = t * 64; tlen = 64; }
    else if (t < 96) { tu0 = 2048 + (t - 32) * 128; tlen = 128; }
    else { tu0 = 10240 + (t - 96) * 64; tlen = 64; }
    int blo = cta_of(tu0), bhi = cta_of(tu0 + tlen - 1);

    int row = threadIdx.x >> 1, cb = (threadIdx.x & 1) * 32;
    float4 a[8];
#pragma unroll
    for (int q = 0; q < 8; q++) a[q] = make_float4(0.f, 0.f, 0.f, 0.f);
    for (int bb = blo; bb <= bhi; bb++) {
        int us = (bb * NUNIT) / NCTA;
        int ft, fc;
        decode_unit(us, ft, fc);
        const float4* p = (const float4*)(g_gpart + ((size_t)(bb * 3 + (t - ft)) << 13) +
                                          row * 64 + cb);
#pragma unroll
        for (int q = 0; q < 8; q++) {
            float4 v = p[q];
            a[q].x += v.x; a[q].y += v.y; a[q].z += v.z; a[q].w += v.w;
        }
    }
    float dv = g_dinv[gb + m0 + row];
    float4* o = (float4*)(xout + (size_t)(gb + m0 + row) * CD + cb);
#pragma unroll
    for (int q = 0; q < 8; q++)
        o[q] = make_float4(fmaxf(dv * a[q].x, 0.f), fmaxf(dv * a[q].y, 0.f),
                           fmaxf(dv * a[q].z, 0.f), fmaxf(dv * a[q].w, 0.f));
}

// ==========================================================================
// Kernel 4: deterministic segment pooling — reads x exactly once.
// ==========================================================================
__global__ void __launch_bounds__(64) pool_kernel(const int* __restrict__ bel0,
                                                  const int* __restrict__ bel1,
                                                  const int* __restrict__ bel2) {
    int blk = blockIdx.x;
    const int* bel;
    int gb, lrow0;
    if (blk < 16) { bel = bel0; gb = 0; lrow0 = blk * 256; }
    else if (blk < 48) { bel = bel1; gb = N0T; lrow0 = (blk - 16) * 256; }
    else { bel = bel2; gb = N0T + N1T; lrow0 = (blk - 48) * 256; }
    int t = threadIdx.x;

    __shared__ float bins[BSEG * CD];
    for (int i = t; i < BSEG * CD; i += 64) bins[i] = 0.f;
    __syncthreads();

    const float* xp = g_xA + (size_t)(gb + lrow0) * CD + t;
    const int* bp = bel + lrow0;
#pragma unroll 4
    for (int i = 0; i < 256; i++) {
        int bseg = __ldg(bp + i);
        float v = __ldg(xp + (size_t)i * CD);
        bins[bseg * CD + t] += v;
    }
    __syncthreads();
    for (int i = t; i < BSEG * CD; i += 64) g_part[blk * (BSEG * CD) + i] = bins[i];
}

// ==========================================================================
// Kernel 5: readout  out[b][o] = sum_r pooled_r @ Wr_r + br_r
// ==========================================================================
__global__ void __launch_bounds__(256) readout_kernel(const float* __restrict__ Wr0,
                                                      const float* __restrict__ br0,
                                                      const float* __restrict__ Wr1,
                                                      const float* __restrict__ br1,
                                                      const float* __restrict__ Wr2,
                                                      const float* __restrict__ br2,
                                                      float* __restrict__ out) {
    __shared__ float ps[3 * 8 * 64];  // [r][b_local][c]
    int tid = threadIdx.x;
    int b0 = blockIdx.x * 8;
    for (int i = tid; i < 1536; i += 256) {
        int r = i / 512;
        int rem = i % 512;
        int bl = rem / 64;
        int c = rem % 64;
        int kb = (r == 0) ? 0 : (r == 1 ? 16 : 48);
        int kn = (r == 1) ? 32 : 16;
        float s = 0.f;
        for (int k = 0; k < kn; k++)
            s += g_part[(kb + k) * (BSEG * CD) + (b0 + bl) * 64 + c];
        ps[i] = s;
    }
    __syncthreads();
    int bl = tid >> 5, o = tid & 31;
    float acc = __ldg(br0 + o) + __ldg(br1 + o) + __ldg(br2 + o);
    const float* Wr[3] = {Wr0, Wr1, Wr2};
#pragma unroll
    for (int r = 0; r < 3; r++) {
        const float* w = Wr[r];
        const float* p = &ps[r * 512 + bl * 64];
#pragma unroll 8
        for (int c = 0; c < 64; c++) acc += p[c] * __ldg(w + c * OUTD + o);
    }
    out[(b0 + bl) * OUTD + o] = acc;
}

// ==========================================================================
// host
// ==========================================================================
extern "C" void kernel_launch(void* const* d_in, const int* in_sizes, int n_in,
                              void* d_out, int out_size) {
    const float* x0 = (const float*)d_in[0];
    const float* x1 = (const float*)d_in[1];
    const float* x2 = (const float*)d_in[2];
    const float* L0 = (const float*)d_in[3];
    const float* L1 = (const float*)d_in[4];
    const float* L2 = (const float*)d_in[5];
    const int* bel0 = (const int*)d_in[6];
    const int* bel1 = (const int*)d_in[7];
    const int* bel2 = (const int*)d_in[8];
    const float* W0 = (const float*)d_in[9];
    const float* W1 = (const float*)d_in[10];
    const float* W2 = (const float*)d_in[11];
    const float* Wr0 = (const float*)d_in[12];
    const float* br0 = (const float*)d_in[13];
    const float* Wr1 = (const float*)d_in[14];
    const float* br1 = (const float*)d_in[15];
    const float* Wr2 = (const float*)d_in[16];
    const float* br2 = (const float*)d_in[17];

    cudaFuncSetAttribute(spmm_kernel, cudaFuncAttributeMaxDynamicSharedMemorySize, SMEMSZ);

    probe_kernel<<<1, 32>>>();  // keeps ncu capture slot on spmm (layer0)
    rowsum_cvt_kernel<<<NTOT, 256>>>(L0, L1, L2);

    for (int layer = 0; layer < 2; layer++) {
        xw_kernel<<<NTOT / 64, 256>>>(W0 + layer * CD * CD, W1 + layer * CD * CD,
                                      W2 + layer * CD * CD, x0, x1, x2, layer);
        spmm_kernel<<<NCTA, 256, SMEMSZ>>>();
        combine_kernel<<<NTILE, 256>>>(layer);
    }

    pool_kernel<<<64, 64>>>(bel0, bel1, bel2);
    readout_kernel<<<8, 256>>>(Wr0, br0, Wr1, br1, Wr2, br2, (float*)d_out);
}